// round 1
// baseline (speedup 1.0000x reference)
#include <cuda_runtime.h>
#include <math.h>

#define HDIM 1024
#define IDIM 2752
#define NE   8
#define NT   4096          // tokens = 4*1024
#define NROUTED (2*NT)     // routed entries
#define NENT (3*NT)        // + shared entries [2T, 3T)

// ---------------- scratch (static device globals; no runtime alloc) -----------
__device__ int   g_counts[NE];
__device__ int   g_off[NE + 1];
__device__ int   g_cursor[NE];
__device__ int   g_topk_idx[NROUTED];
__device__ float g_topk_w[NROUTED];
__device__ int   g_perm[NROUTED];      // entry -> token
__device__ float g_wgt[NROUTED];       // entry -> routing weight
__device__ int   g_entry_of[NROUTED];  // (t,k) -> entry
__device__ float g_hmid[(size_t)NENT * IDIM];  // ~135 MB
__device__ float g_eo[(size_t)NENT * HDIM];    // ~50 MB

// ---------------- init ----------------
__global__ void init_kernel() {
    int i = threadIdx.x;
    if (i < NE) g_counts[i] = 0;
}

// ---------------- gating: one warp per token ----------------
__global__ void gate_kernel(const float* __restrict__ x,
                            const float* __restrict__ gw) {
    int warp = (blockIdx.x * blockDim.x + threadIdx.x) >> 5;
    int lane = threadIdx.x & 31;
    if (warp >= NT) return;
    const float4* x4  = (const float4*)(x + (size_t)warp * HDIM);
    const float4* gw4 = (const float4*)gw;

    float acc[NE];
#pragma unroll
    for (int e = 0; e < NE; e++) acc[e] = 0.f;

    for (int h4 = lane; h4 < HDIM / 4; h4 += 32) {
        float4 xv = x4[h4];
#pragma unroll
        for (int e = 0; e < NE; e++) {
            float4 g = gw4[e * (HDIM / 4) + h4];
            acc[e] += xv.x * g.x + xv.y * g.y + xv.z * g.z + xv.w * g.w;
        }
    }
#pragma unroll
    for (int e = 0; e < NE; e++) {
#pragma unroll
        for (int off = 16; off > 0; off >>= 1)
            acc[e] += __shfl_down_sync(0xffffffffu, acc[e], off);
    }
    if (lane == 0) {
        // softmax over 8
        float mx = acc[0];
#pragma unroll
        for (int e = 1; e < NE; e++) mx = fmaxf(mx, acc[e]);
        float p[NE], s = 0.f;
#pragma unroll
        for (int e = 0; e < NE; e++) { p[e] = expf(acc[e] - mx); s += p[e]; }
        float inv = 1.f / s;
#pragma unroll
        for (int e = 0; e < NE; e++) p[e] *= inv;
        // top-2 (lowest index wins ties, matching lax.top_k)
        int i1 = 0; float p1 = p[0];
#pragma unroll
        for (int e = 1; e < NE; e++) if (p[e] > p1) { p1 = p[e]; i1 = e; }
        int i2 = -1; float p2 = -1.f;
#pragma unroll
        for (int e = 0; e < NE; e++) {
            if (e == i1) continue;
            if (p[e] > p2) { p2 = p[e]; i2 = e; }
        }
        float rn = 1.f / (p1 + p2 + 1e-20f);
        g_topk_idx[2 * warp + 0] = i1;
        g_topk_idx[2 * warp + 1] = i2;
        g_topk_w[2 * warp + 0] = p1 * rn;
        g_topk_w[2 * warp + 1] = p2 * rn;
        atomicAdd(&g_counts[i1], 1);
        atomicAdd(&g_counts[i2], 1);
    }
}

// ---------------- scan ----------------
__global__ void scan_kernel() {
    if (threadIdx.x == 0) {
        int s = 0;
        for (int e = 0; e < NE; e++) { g_off[e] = s; s += g_counts[e]; }
        g_off[NE] = s;
        for (int e = 0; e < NE; e++) g_cursor[e] = g_off[e];
    }
}

// ---------------- scatter ----------------
__global__ void scatter_kernel() {
    int i = blockIdx.x * blockDim.x + threadIdx.x;
    if (i >= NROUTED) return;
    int t = i >> 1;
    int e = g_topk_idx[i];
    int pos = atomicAdd(&g_cursor[e], 1);
    g_perm[pos] = t;
    g_wgt[pos] = g_topk_w[i];
    g_entry_of[i] = pos;
}

// ---------------- grouped gate+up GEMM, fused SiLU ----------------
// C[m][n] over experts: A = gathered x rows [M x H], B = w [I x H] (K-major both)
#define BM 64
#define BN 64
#define BK 16

__global__ __launch_bounds__(256) void gateup_kernel(
    const float* __restrict__ x,
    const float* __restrict__ w_gate, const float* __restrict__ w_up,
    const float* __restrict__ ws_gate, const float* __restrict__ ws_up) {
    int e = blockIdx.z;
    int M, base;
    const float *Bg, *Bu;
    bool is_shared = (e == NE);
    if (!is_shared) {
        base = g_off[e];
        M = g_off[e + 1] - base;
        Bg = w_gate + (size_t)e * IDIM * HDIM;
        Bu = w_up + (size_t)e * IDIM * HDIM;
    } else {
        base = 2 * NT; M = NT; Bg = ws_gate; Bu = ws_up;
    }
    int m0 = blockIdx.y * BM;
    if (m0 >= M) return;
    int n0 = blockIdx.x * BN;

    __shared__ __align__(16) float As[BK][BM];
    __shared__ __align__(16) float Bgs[BK][BN];
    __shared__ __align__(16) float Bus[BK][BN];

    int tid = threadIdx.x;
    int lrow = tid >> 2;           // 0..63
    int lk   = (tid & 3) * 4;      // 0,4,8,12

    const float* arow = nullptr;
    {
        int gm = m0 + lrow;
        if (gm < M) {
            int tok = is_shared ? gm : g_perm[base + gm];
            arow = x + (size_t)tok * HDIM;
        }
    }
    const float* bgrow = Bg + (size_t)(n0 + lrow) * HDIM;
    const float* burow = Bu + (size_t)(n0 + lrow) * HDIM;

    int ty = tid >> 4;   // 0..15
    int tx = tid & 15;   // 0..15
    float accg[4][4] = {{0}}, accu[4][4] = {{0}};

    for (int k0 = 0; k0 < HDIM; k0 += BK) {
        float4 av = arow ? *(const float4*)(arow + k0 + lk)
                         : make_float4(0.f, 0.f, 0.f, 0.f);
        float4 bgv = *(const float4*)(bgrow + k0 + lk);
        float4 buv = *(const float4*)(burow + k0 + lk);
        __syncthreads();
        As[lk + 0][lrow] = av.x;  As[lk + 1][lrow] = av.y;
        As[lk + 2][lrow] = av.z;  As[lk + 3][lrow] = av.w;
        Bgs[lk + 0][lrow] = bgv.x; Bgs[lk + 1][lrow] = bgv.y;
        Bgs[lk + 2][lrow] = bgv.z; Bgs[lk + 3][lrow] = bgv.w;
        Bus[lk + 0][lrow] = buv.x; Bus[lk + 1][lrow] = buv.y;
        Bus[lk + 2][lrow] = buv.z; Bus[lk + 3][lrow] = buv.w;
        __syncthreads();
#pragma unroll
        for (int k = 0; k < BK; k++) {
            float4 a  = *(const float4*)&As[k][ty * 4];
            float4 bg = *(const float4*)&Bgs[k][tx * 4];
            float4 bu = *(const float4*)&Bus[k][tx * 4];
            float ar[4] = {a.x, a.y, a.z, a.w};
            float bgr[4] = {bg.x, bg.y, bg.z, bg.w};
            float bur[4] = {bu.x, bu.y, bu.z, bu.w};
#pragma unroll
            for (int i = 0; i < 4; i++)
#pragma unroll
                for (int j = 0; j < 4; j++) {
                    accg[i][j] += ar[i] * bgr[j];
                    accu[i][j] += ar[i] * bur[j];
                }
        }
    }
    // epilogue: hmid = silu(g) * u
#pragma unroll
    for (int i = 0; i < 4; i++) {
        int gm = m0 + ty * 4 + i;
        if (gm >= M) continue;
        size_t row = (size_t)(base + gm) * IDIM;
#pragma unroll
        for (int j = 0; j < 4; j++) {
            float g = accg[i][j];
            float u = accu[i][j];
            float s = g / (1.f + expf(-g));
            g_hmid[row + n0 + tx * 4 + j] = s * u;
        }
    }
}

// ---------------- down GEMM (K = IDIM), scaled by routing weight ----------------
__global__ __launch_bounds__(256) void down_kernel(
    const float* __restrict__ w_down, const float* __restrict__ ws_down) {
    int e = blockIdx.z;
    int M, base;
    const float* Bw;
    bool is_shared = (e == NE);
    if (!is_shared) {
        base = g_off[e];
        M = g_off[e + 1] - base;
        Bw = w_down + (size_t)e * HDIM * IDIM;
    } else {
        base = 2 * NT; M = NT; Bw = ws_down;
    }
    int m0 = blockIdx.y * BM;
    if (m0 >= M) return;
    int n0 = blockIdx.x * BN;

    __shared__ __align__(16) float As[BK][BM];
    __shared__ __align__(16) float Bs[BK][BN];

    int tid = threadIdx.x;
    int lrow = tid >> 2;
    int lk   = (tid & 3) * 4;

    const float* arow = nullptr;
    {
        int gm = m0 + lrow;
        if (gm < M) arow = g_hmid + (size_t)(base + gm) * IDIM;
    }
    const float* brow = Bw + (size_t)(n0 + lrow) * IDIM;

    int ty = tid >> 4;
    int tx = tid & 15;
    float acc[4][4] = {{0}};

    for (int k0 = 0; k0 < IDIM; k0 += BK) {
        float4 av = arow ? *(const float4*)(arow + k0 + lk)
                         : make_float4(0.f, 0.f, 0.f, 0.f);
        float4 bv = *(const float4*)(brow + k0 + lk);
        __syncthreads();
        As[lk + 0][lrow] = av.x; As[lk + 1][lrow] = av.y;
        As[lk + 2][lrow] = av.z; As[lk + 3][lrow] = av.w;
        Bs[lk + 0][lrow] = bv.x; Bs[lk + 1][lrow] = bv.y;
        Bs[lk + 2][lrow] = bv.z; Bs[lk + 3][lrow] = bv.w;
        __syncthreads();
#pragma unroll
        for (int k = 0; k < BK; k++) {
            float4 a = *(const float4*)&As[k][ty * 4];
            float4 b = *(const float4*)&Bs[k][tx * 4];
            float ar[4] = {a.x, a.y, a.z, a.w};
            float br[4] = {b.x, b.y, b.z, b.w};
#pragma unroll
            for (int i = 0; i < 4; i++)
#pragma unroll
                for (int j = 0; j < 4; j++)
                    acc[i][j] += ar[i] * br[j];
        }
    }
#pragma unroll
    for (int i = 0; i < 4; i++) {
        int gm = m0 + ty * 4 + i;
        if (gm >= M) continue;
        float w = is_shared ? 1.f : g_wgt[base + gm];
        size_t row = (size_t)(base + gm) * HDIM;
#pragma unroll
        for (int j = 0; j < 4; j++)
            g_eo[row + n0 + tx * 4 + j] = acc[i][j] * w;
    }
}

// ---------------- combine ----------------
__global__ void combine_kernel(float* __restrict__ out) {
    int idx = blockIdx.x * blockDim.x + threadIdx.x;   // over T*H/4
    const int HC = HDIM / 4;
    if (idx >= NT * HC) return;
    int t = idx / HC;
    int c = idx - t * HC;
    const float4* eo4 = (const float4*)g_eo;
    int e1 = g_entry_of[2 * t + 0];
    int e2 = g_entry_of[2 * t + 1];
    float4 a = eo4[(size_t)e1 * HC + c];
    float4 b = eo4[(size_t)e2 * HC + c];
    float4 s = eo4[(size_t)(2 * NT + t) * HC + c];
    float4 r;
    r.x = a.x + b.x + s.x;
    r.y = a.y + b.y + s.y;
    r.z = a.z + b.z + s.z;
    r.w = a.w + b.w + s.w;
    ((float4*)out)[idx] = r;
}

// ---------------- launch ----------------
extern "C" void kernel_launch(void* const* d_in, const int* in_sizes, int n_in,
                              void* d_out, int out_size) {
    const float* x       = (const float*)d_in[0];
    const float* gate_w  = (const float*)d_in[1];
    const float* w_gate  = (const float*)d_in[2];
    const float* w_up    = (const float*)d_in[3];
    const float* w_down  = (const float*)d_in[4];
    const float* ws_gate = (const float*)d_in[5];
    const float* ws_up   = (const float*)d_in[6];
    const float* ws_down = (const float*)d_in[7];
    float* out = (float*)d_out;

    init_kernel<<<1, 32>>>();
    gate_kernel<<<NT / 8, 256>>>(x, gate_w);
    scan_kernel<<<1, 32>>>();
    scatter_kernel<<<(NROUTED + 255) / 256, 256>>>();
    gateup_kernel<<<dim3(IDIM / BN, NT / BM, NE + 1), 256>>>(x, w_gate, w_up,
                                                             ws_gate, ws_up);
    down_kernel<<<dim3(HDIM / BN, NT / BM, NE + 1), 256>>>(w_down, ws_down);
    combine_kernel<<<(NT * (HDIM / 4) + 255) / 256, 256>>>(out);
}

// round 3
// speedup vs baseline: 2.2907x; 2.2907x over previous
#include <cuda_runtime.h>
#include <cuda_bf16.h>
#include <math.h>
#include <stdint.h>

#define HDIM 1024
#define IDIM 2752
#define NE   8
#define NT   4096
#define NROUTED (2*NT)
#define NRP  9216
#define SHB  9216
#define NEP  (NRP + NT)
#define MAXTILES 72

// ---------------- scratch ----------------
__device__ int   g_counts[NE];
__device__ int   g_offp[NE];
__device__ int   g_cursor[NE];
__device__ int   g_tile_e[MAXTILES];
__device__ int   g_tile_m[MAXTILES];
__device__ int   g_topk_idx[NROUTED];
__device__ float g_topk_w[NROUTED];
__device__ int   g_perm[NRP];
__device__ float g_wgt[NRP];
__device__ int   g_entry_of[NROUTED];

__device__ __nv_bfloat16 g_xh[(size_t)NT * HDIM];
__device__ __nv_bfloat16 g_xl[(size_t)NT * HDIM];
__device__ __nv_bfloat16 g_wgh[(size_t)NE * IDIM * HDIM];
__device__ __nv_bfloat16 g_wgl[(size_t)NE * IDIM * HDIM];
__device__ __nv_bfloat16 g_wuh[(size_t)NE * IDIM * HDIM];
__device__ __nv_bfloat16 g_wul[(size_t)NE * IDIM * HDIM];
__device__ __nv_bfloat16 g_wdh[(size_t)NE * HDIM * IDIM];
__device__ __nv_bfloat16 g_wdl[(size_t)NE * HDIM * IDIM];
__device__ __nv_bfloat16 g_sgh[(size_t)IDIM * HDIM];
__device__ __nv_bfloat16 g_sgl[(size_t)IDIM * HDIM];
__device__ __nv_bfloat16 g_suh[(size_t)IDIM * HDIM];
__device__ __nv_bfloat16 g_sul[(size_t)IDIM * HDIM];
__device__ __nv_bfloat16 g_sdh[(size_t)HDIM * IDIM];
__device__ __nv_bfloat16 g_sdl[(size_t)HDIM * IDIM];
__device__ __nv_bfloat16 g_hmh[(size_t)NEP * IDIM];
__device__ __nv_bfloat16 g_hml[(size_t)NEP * IDIM];
__device__ float         g_eo[(size_t)NEP * HDIM];

// ---------------- helpers ----------------
__device__ __forceinline__ uint32_t smem_u32(const void* p) {
    uint32_t a;
    asm("{ .reg .u64 t; cvta.to.shared.u64 t, %1; cvt.u32.u64 %0, t; }"
        : "=r"(a) : "l"(p));
    return a;
}
__device__ __forceinline__ void ldsm4(uint32_t* r, uint32_t a) {
    asm volatile("ldmatrix.sync.aligned.m8n8.x4.shared.b16 {%0,%1,%2,%3}, [%4];"
                 : "=r"(r[0]), "=r"(r[1]), "=r"(r[2]), "=r"(r[3]) : "r"(a));
}
__device__ __forceinline__ void mma16816(float* c, const uint32_t* a,
                                         uint32_t b0, uint32_t b1) {
    asm volatile(
        "mma.sync.aligned.m16n8k16.row.col.f32.bf16.bf16.f32 "
        "{%0,%1,%2,%3}, {%4,%5,%6,%7}, {%8,%9}, {%0,%1,%2,%3};"
        : "+f"(c[0]), "+f"(c[1]), "+f"(c[2]), "+f"(c[3])
        : "r"(a[0]), "r"(a[1]), "r"(a[2]), "r"(a[3]), "r"(b0), "r"(b1));
}
__device__ __forceinline__ void cpasync16(uint32_t dst, const void* src) {
    asm volatile("cp.async.cg.shared.global [%0], [%1], 16;" :: "r"(dst), "l"(src));
}
#define CP_COMMIT() asm volatile("cp.async.commit_group;" ::: "memory")
#define CP_WAIT1()  asm volatile("cp.async.wait_group 1;" ::: "memory")
#define CP_WAIT0()  asm volatile("cp.async.wait_group 0;" ::: "memory")

__device__ __forceinline__ uint32_t pack_hilo(float a, float b, uint32_t& lo) {
    __nv_bfloat16 ha = __float2bfloat16(a), hb = __float2bfloat16(b);
    __nv_bfloat16 la = __float2bfloat16(a - __bfloat162float(ha));
    __nv_bfloat16 lb = __float2bfloat16(b - __bfloat162float(hb));
    lo = ((uint32_t)__bfloat16_as_ushort(lb) << 16) | __bfloat16_as_ushort(la);
    return ((uint32_t)__bfloat16_as_ushort(hb) << 16) | __bfloat16_as_ushort(ha);
}

// ---------------- small kernels ----------------
__global__ void init_kernel() {
    int i = threadIdx.x;
    if (i < NE) g_counts[i] = 0;
}

__global__ void conv_kernel(const float* __restrict__ src,
                            __nv_bfloat16* __restrict__ h,
                            __nv_bfloat16* __restrict__ l, int n4) {
    int i = blockIdx.x * blockDim.x + threadIdx.x;
    if (i >= n4) return;
    float4 v = ((const float4*)src)[i];
    uint32_t l0, l1;
    uint32_t h0 = pack_hilo(v.x, v.y, l0);
    uint32_t h1 = pack_hilo(v.z, v.w, l1);
    uint2 ph, pl;
    ph.x = h0; ph.y = h1;
    pl.x = l0; pl.y = l1;
    ((uint2*)h)[i] = ph;
    ((uint2*)l)[i] = pl;
}

__global__ void gate_kernel(const float* __restrict__ x,
                            const float* __restrict__ gw) {
    int warp = (blockIdx.x * blockDim.x + threadIdx.x) >> 5;
    int lane = threadIdx.x & 31;
    if (warp >= NT) return;
    const float4* x4 = (const float4*)(x + (size_t)warp * HDIM);
    const float4* gw4 = (const float4*)gw;
    float acc[NE];
#pragma unroll
    for (int e = 0; e < NE; e++) acc[e] = 0.f;
    for (int h4 = lane; h4 < HDIM / 4; h4 += 32) {
        float4 xv = x4[h4];
#pragma unroll
        for (int e = 0; e < NE; e++) {
            float4 g = gw4[e * (HDIM / 4) + h4];
            acc[e] += xv.x * g.x + xv.y * g.y + xv.z * g.z + xv.w * g.w;
        }
    }
#pragma unroll
    for (int e = 0; e < NE; e++)
#pragma unroll
        for (int off = 16; off > 0; off >>= 1)
            acc[e] += __shfl_down_sync(0xffffffffu, acc[e], off);
    if (lane == 0) {
        float mx = acc[0];
#pragma unroll
        for (int e = 1; e < NE; e++) mx = fmaxf(mx, acc[e]);
        float p[NE], s = 0.f;
#pragma unroll
        for (int e = 0; e < NE; e++) { p[e] = expf(acc[e] - mx); s += p[e]; }
        float inv = 1.f / s;
#pragma unroll
        for (int e = 0; e < NE; e++) p[e] *= inv;
        int i1 = 0; float p1 = p[0];
#pragma unroll
        for (int e = 1; e < NE; e++) if (p[e] > p1) { p1 = p[e]; i1 = e; }
        int i2 = -1; float p2 = -1.f;
#pragma unroll
        for (int e = 0; e < NE; e++) {
            if (e == i1) continue;
            if (p[e] > p2) { p2 = p[e]; i2 = e; }
        }
        float rn = 1.f / (p1 + p2 + 1e-20f);
        g_topk_idx[2 * warp + 0] = i1;
        g_topk_idx[2 * warp + 1] = i2;
        g_topk_w[2 * warp + 0] = p1 * rn;
        g_topk_w[2 * warp + 1] = p2 * rn;
        atomicAdd(&g_counts[i1], 1);
        atomicAdd(&g_counts[i2], 1);
    }
}

__global__ void scan_kernel() {
    if (threadIdx.x == 0) {
        int s = 0, t = 0;
        for (int e = 0; e < NE; e++) {
            g_offp[e] = s;
            g_cursor[e] = s;
            int c = g_counts[e];
            int nt = (c + 127) >> 7;
            for (int m = 0; m < nt; m++) { g_tile_e[t] = e; g_tile_m[t] = m << 7; t++; }
            s += (c + 127) & ~127;
        }
        for (; t < MAXTILES; t++) g_tile_e[t] = -1;
    }
}

__global__ void scatter_kernel() {
    int i = blockIdx.x * blockDim.x + threadIdx.x;
    if (i >= NROUTED) return;
    int t = i >> 1;
    int e = g_topk_idx[i];
    int pos = atomicAdd(&g_cursor[e], 1);
    g_perm[pos] = t;
    g_wgt[pos] = g_topk_w[i];
    g_entry_of[i] = pos;
}

// ---------------- gate+up MMA GEMM ----------------
// block 128x128 (x2 outputs), 8 warps (64x32 warp tiles), BK=64, hi/lo 3-pass
#define GU_PART  16384
#define GU_STAGE (6 * GU_PART)
#define GU_SMEM  (2 * GU_STAGE)

__global__ __launch_bounds__(256, 1) void gateup_mma() {
    extern __shared__ char sm[];
    uint32_t sb = smem_u32(sm);
    int tid = threadIdx.x, wid = tid >> 5, lane = tid & 31;

    int y = blockIdx.y;
    int e, m0, base;
    bool is_shared;
    if (y >= MAXTILES) {
        is_shared = true; m0 = (y - MAXTILES) << 7; base = SHB;
    } else {
        e = g_tile_e[y];
        if (e < 0) return;
        is_shared = false; m0 = g_tile_m[y]; base = g_offp[e];
    }
    int n0 = blockIdx.x * 128;

    const __nv_bfloat16* WGH = is_shared ? g_sgh : g_wgh + (size_t)e * IDIM * HDIM;
    const __nv_bfloat16* WGL = is_shared ? g_sgl : g_wgl + (size_t)e * IDIM * HDIM;
    const __nv_bfloat16* WUH = is_shared ? g_suh : g_wuh + (size_t)e * IDIM * HDIM;
    const __nv_bfloat16* WUL = is_shared ? g_sul : g_wul + (size_t)e * IDIM * HDIM;

    // gmem->smem mapping: thread -> (row = tid>>1, 4 chunks of 16B)
    int lrow = tid >> 1, kb0 = (tid & 1) * 4;
    uint32_t swo[4];
#pragma unroll
    for (int j = 0; j < 4; j++)
        swo[j] = lrow * 128 + (((kb0 + j) ^ (lrow & 7)) << 4);
    int tok = is_shared ? (m0 + lrow) : g_perm[base + m0 + lrow];
    const __nv_bfloat16* pAh = g_xh + (size_t)tok * HDIM + kb0 * 8;
    const __nv_bfloat16* pAl = g_xl + (size_t)tok * HDIM + kb0 * 8;
    int nr = n0 + lrow; if (nr > IDIM - 1) nr = IDIM - 1;
    const __nv_bfloat16* pGh = WGH + (size_t)nr * HDIM + kb0 * 8;
    const __nv_bfloat16* pGl = WGL + (size_t)nr * HDIM + kb0 * 8;
    const __nv_bfloat16* pUh = WUH + (size_t)nr * HDIM + kb0 * 8;
    const __nv_bfloat16* pUl = WUL + (size_t)nr * HDIM + kb0 * 8;

    auto issue = [&](int s) {
        int k0 = s * 64;
        uint32_t bb = sb + (s & 1) * GU_STAGE;
#pragma unroll
        for (int j = 0; j < 4; j++) {
            cpasync16(bb + 0 * GU_PART + swo[j], pAh + k0 + j * 8);
            cpasync16(bb + 1 * GU_PART + swo[j], pAl + k0 + j * 8);
            cpasync16(bb + 2 * GU_PART + swo[j], pGh + k0 + j * 8);
            cpasync16(bb + 3 * GU_PART + swo[j], pGl + k0 + j * 8);
            cpasync16(bb + 4 * GU_PART + swo[j], pUh + k0 + j * 8);
            cpasync16(bb + 5 * GU_PART + swo[j], pUl + k0 + j * 8);
        }
    };

    // warp tiling
    int warpM = (wid & 1) * 64;
    int warpN = (wid >> 1) * 32;
    int la = lane & 15, kh = lane >> 4, x7 = la & 7;
    uint32_t rowA[4], rowB[2];
#pragma unroll
    for (int mf = 0; mf < 4; mf++) rowA[mf] = (warpM + mf * 16 + la) * 128;
#pragma unroll
    for (int s2 = 0; s2 < 2; s2++) rowB[s2] = (warpN + s2 * 16 + la) * 128;

    float aG[4][4][4], aU[4][4][4];
#pragma unroll
    for (int mf = 0; mf < 4; mf++)
#pragma unroll
        for (int nf = 0; nf < 4; nf++)
#pragma unroll
            for (int q = 0; q < 4; q++) { aG[mf][nf][q] = 0.f; aU[mf][nf][q] = 0.f; }

    issue(0); CP_COMMIT();
    for (int s = 0; s < 16; s++) {
        if (s < 15) { issue(s + 1); CP_COMMIT(); CP_WAIT1(); }
        else CP_WAIT0();
        __syncthreads();
        uint32_t bb = sb + (s & 1) * GU_STAGE;
#pragma unroll
        for (int k16 = 0; k16 < 4; k16++) {
            uint32_t ko = (uint32_t)(((k16 * 2 + kh) ^ x7) << 4);
            uint32_t Ah[4][4], Al[4][4];
#pragma unroll
            for (int mf = 0; mf < 4; mf++) {
                ldsm4(Ah[mf], bb + 0 * GU_PART + rowA[mf] + ko);
                ldsm4(Al[mf], bb + 1 * GU_PART + rowA[mf] + ko);
            }
            uint32_t Gh[2][4], Gl2[2][4], Uh[2][4], Ul2[2][4];
#pragma unroll
            for (int s2 = 0; s2 < 2; s2++) {
                ldsm4(Gh[s2],  bb + 2 * GU_PART + rowB[s2] + ko);
                ldsm4(Gl2[s2], bb + 3 * GU_PART + rowB[s2] + ko);
                ldsm4(Uh[s2],  bb + 4 * GU_PART + rowB[s2] + ko);
                ldsm4(Ul2[s2], bb + 5 * GU_PART + rowB[s2] + ko);
            }
#pragma unroll
            for (int mf = 0; mf < 4; mf++)
#pragma unroll
                for (int s2 = 0; s2 < 2; s2++)
#pragma unroll
                    for (int j = 0; j < 2; j++) {
                        int nf = s2 * 2 + j;
                        mma16816(aG[mf][nf], Ah[mf], Gh[s2][j],  Gh[s2][2 + j]);
                        mma16816(aG[mf][nf], Al[mf], Gh[s2][j],  Gh[s2][2 + j]);
                        mma16816(aG[mf][nf], Ah[mf], Gl2[s2][j], Gl2[s2][2 + j]);
                        mma16816(aU[mf][nf], Ah[mf], Uh[s2][j],  Uh[s2][2 + j]);
                        mma16816(aU[mf][nf], Al[mf], Uh[s2][j],  Uh[s2][2 + j]);
                        mma16816(aU[mf][nf], Ah[mf], Ul2[s2][j], Ul2[s2][2 + j]);
                    }
        }
        __syncthreads();
    }

    // epilogue: hmid = silu(g)*u, hi/lo bf16
    int qr = lane >> 2, qc = (lane & 3) * 2;
#pragma unroll
    for (int mf = 0; mf < 4; mf++)
#pragma unroll
        for (int nf = 0; nf < 4; nf++) {
            int col = n0 + warpN + nf * 8 + qc;
            if (col >= IDIM) continue;
            float* cg = aG[mf][nf];
            float* cu = aU[mf][nf];
            int r0 = m0 + warpM + mf * 16 + qr;
            float g0 = cg[0], g1 = cg[1], g2 = cg[2], g3 = cg[3];
            float v00 = (g0 / (1.f + expf(-g0))) * cu[0];
            float v01 = (g1 / (1.f + expf(-g1))) * cu[1];
            float v10 = (g2 / (1.f + expf(-g2))) * cu[2];
            float v11 = (g3 / (1.f + expf(-g3))) * cu[3];
            uint32_t lo0, lo1;
            uint32_t hi0 = pack_hilo(v00, v01, lo0);
            uint32_t hi1 = pack_hilo(v10, v11, lo1);
            size_t o0 = (size_t)(base + r0) * IDIM + col;
            size_t o1 = o0 + (size_t)8 * IDIM;
            *(uint32_t*)(g_hmh + o0) = hi0;
            *(uint32_t*)(g_hml + o0) = lo0;
            *(uint32_t*)(g_hmh + o1) = hi1;
            *(uint32_t*)(g_hml + o1) = lo1;
        }
}

// ---------------- down MMA GEMM ----------------
#define DN_PART  16384
#define DN_STAGE (4 * DN_PART)
#define DN_SMEM  (2 * DN_STAGE)

__global__ __launch_bounds__(256, 1) void down_mma() {
    extern __shared__ char sm[];
    uint32_t sb = smem_u32(sm);
    int tid = threadIdx.x, wid = tid >> 5, lane = tid & 31;

    int y = blockIdx.y;
    int e, m0, base;
    bool is_shared;
    if (y >= MAXTILES) {
        is_shared = true; m0 = (y - MAXTILES) << 7; base = SHB;
    } else {
        e = g_tile_e[y];
        if (e < 0) return;
        is_shared = false; m0 = g_tile_m[y]; base = g_offp[e];
    }
    int n0 = blockIdx.x * 128;

    const __nv_bfloat16* WDH = is_shared ? g_sdh : g_wdh + (size_t)e * HDIM * IDIM;
    const __nv_bfloat16* WDL = is_shared ? g_sdl : g_wdl + (size_t)e * HDIM * IDIM;

    int lrow = tid >> 1, kb0 = (tid & 1) * 4;
    uint32_t swo[4];
#pragma unroll
    for (int j = 0; j < 4; j++)
        swo[j] = lrow * 128 + (((kb0 + j) ^ (lrow & 7)) << 4);
    const __nv_bfloat16* pAh = g_hmh + (size_t)(base + m0 + lrow) * IDIM + kb0 * 8;
    const __nv_bfloat16* pAl = g_hml + (size_t)(base + m0 + lrow) * IDIM + kb0 * 8;
    const __nv_bfloat16* pBh = WDH + (size_t)(n0 + lrow) * IDIM + kb0 * 8;
    const __nv_bfloat16* pBl = WDL + (size_t)(n0 + lrow) * IDIM + kb0 * 8;

    auto issue = [&](int s) {
        int k0 = s * 64;
        uint32_t bb = sb + (s & 1) * DN_STAGE;
#pragma unroll
        for (int j = 0; j < 4; j++) {
            cpasync16(bb + 0 * DN_PART + swo[j], pAh + k0 + j * 8);
            cpasync16(bb + 1 * DN_PART + swo[j], pAl + k0 + j * 8);
            cpasync16(bb + 2 * DN_PART + swo[j], pBh + k0 + j * 8);
            cpasync16(bb + 3 * DN_PART + swo[j], pBl + k0 + j * 8);
        }
    };

    int warpM = (wid & 1) * 64;
    int warpN = (wid >> 1) * 32;
    int la = lane & 15, kh = lane >> 4, x7 = la & 7;
    uint32_t rowA[4], rowB[2];
#pragma unroll
    for (int mf = 0; mf < 4; mf++) rowA[mf] = (warpM + mf * 16 + la) * 128;
#pragma unroll
    for (int s2 = 0; s2 < 2; s2++) rowB[s2] = (warpN + s2 * 16 + la) * 128;

    float acc[4][4][4];
#pragma unroll
    for (int mf = 0; mf < 4; mf++)
#pragma unroll
        for (int nf = 0; nf < 4; nf++)
#pragma unroll
            for (int q = 0; q < 4; q++) acc[mf][nf][q] = 0.f;

    const int S = IDIM / 64;   // 43
    issue(0); CP_COMMIT();
    for (int s = 0; s < S; s++) {
        if (s < S - 1) { issue(s + 1); CP_COMMIT(); CP_WAIT1(); }
        else CP_WAIT0();
        __syncthreads();
        uint32_t bb = sb + (s & 1) * DN_STAGE;
#pragma unroll
        for (int k16 = 0; k16 < 4; k16++) {
            uint32_t ko = (uint32_t)(((k16 * 2 + kh) ^ x7) << 4);
            uint32_t Ah[4][4], Al[4][4];
#pragma unroll
            for (int mf = 0; mf < 4; mf++) {
                ldsm4(Ah[mf], bb + 0 * DN_PART + rowA[mf] + ko);
                ldsm4(Al[mf], bb + 1 * DN_PART + rowA[mf] + ko);
            }
            uint32_t Bh[2][4], Bl[2][4];
#pragma unroll
            for (int s2 = 0; s2 < 2; s2++) {
                ldsm4(Bh[s2], bb + 2 * DN_PART + rowB[s2] + ko);
                ldsm4(Bl[s2], bb + 3 * DN_PART + rowB[s2] + ko);
            }
#pragma unroll
            for (int mf = 0; mf < 4; mf++)
#pragma unroll
                for (int s2 = 0; s2 < 2; s2++)
#pragma unroll
                    for (int j = 0; j < 2; j++) {
                        int nf = s2 * 2 + j;
                        mma16816(acc[mf][nf], Ah[mf], Bh[s2][j], Bh[s2][2 + j]);
                        mma16816(acc[mf][nf], Al[mf], Bh[s2][j], Bh[s2][2 + j]);
                        mma16816(acc[mf][nf], Ah[mf], Bl[s2][j], Bl[s2][2 + j]);
                    }
        }
        __syncthreads();
    }

    int qr = lane >> 2, qc = (lane & 3) * 2;
#pragma unroll
    for (int mf = 0; mf < 4; mf++) {
        int r0 = m0 + warpM + mf * 16 + qr;
        float w0 = is_shared ? 1.f : g_wgt[base + r0];
        float w1 = is_shared ? 1.f : g_wgt[base + r0 + 8];
#pragma unroll
        for (int nf = 0; nf < 4; nf++) {
            int col = n0 + warpN + nf * 8 + qc;
            float* c = acc[mf][nf];
            size_t o0 = (size_t)(base + r0) * HDIM + col;
            size_t o1 = o0 + (size_t)8 * HDIM;
            float2 v0 = make_float2(c[0] * w0, c[1] * w0);
            float2 v1 = make_float2(c[2] * w1, c[3] * w1);
            *(float2*)(g_eo + o0) = v0;
            *(float2*)(g_eo + o1) = v1;
        }
    }
}

// ---------------- combine ----------------
__global__ void combine_kernel(float* __restrict__ out) {
    int idx = blockIdx.x * blockDim.x + threadIdx.x;
    const int HC = HDIM / 4;
    if (idx >= NT * HC) return;
    int t = idx / HC;
    int c = idx - t * HC;
    const float4* eo4 = (const float4*)g_eo;
    int e1 = g_entry_of[2 * t + 0];
    int e2 = g_entry_of[2 * t + 1];
    float4 a = eo4[(size_t)e1 * HC + c];
    float4 b = eo4[(size_t)e2 * HC + c];
    float4 s = eo4[(size_t)(SHB + t) * HC + c];
    float4 r;
    r.x = a.x + b.x + s.x;
    r.y = a.y + b.y + s.y;
    r.z = a.z + b.z + s.z;
    r.w = a.w + b.w + s.w;
    ((float4*)out)[idx] = r;
}

// ---------------- launch ----------------
extern "C" void kernel_launch(void* const* d_in, const int* in_sizes, int n_in,
                              void* d_out, int out_size) {
    const float* x       = (const float*)d_in[0];
    const float* gate_w  = (const float*)d_in[1];
    const float* w_gate  = (const float*)d_in[2];
    const float* w_up    = (const float*)d_in[3];
    const float* w_down  = (const float*)d_in[4];
    const float* ws_gate = (const float*)d_in[5];
    const float* ws_up   = (const float*)d_in[6];
    const float* ws_down = (const float*)d_in[7];
    float* out = (float*)d_out;

    cudaFuncSetAttribute(gateup_mma, cudaFuncAttributeMaxDynamicSharedMemorySize, GU_SMEM);
    cudaFuncSetAttribute(down_mma,   cudaFuncAttributeMaxDynamicSharedMemorySize, DN_SMEM);

    __nv_bfloat16 *xh, *xl, *wgh, *wgl, *wuh, *wul, *wdh, *wdl;
    __nv_bfloat16 *sgh, *sgl, *suh, *sul, *sdh, *sdl;
    cudaGetSymbolAddress((void**)&xh, g_xh);   cudaGetSymbolAddress((void**)&xl, g_xl);
    cudaGetSymbolAddress((void**)&wgh, g_wgh); cudaGetSymbolAddress((void**)&wgl, g_wgl);
    cudaGetSymbolAddress((void**)&wuh, g_wuh); cudaGetSymbolAddress((void**)&wul, g_wul);
    cudaGetSymbolAddress((void**)&wdh, g_wdh); cudaGetSymbolAddress((void**)&wdl, g_wdl);
    cudaGetSymbolAddress((void**)&sgh, g_sgh); cudaGetSymbolAddress((void**)&sgl, g_sgl);
    cudaGetSymbolAddress((void**)&suh, g_suh); cudaGetSymbolAddress((void**)&sul, g_sul);
    cudaGetSymbolAddress((void**)&sdh, g_sdh); cudaGetSymbolAddress((void**)&sdl, g_sdl);

    init_kernel<<<1, 32>>>();
    const int CT = 256;
    int n4;
    n4 = NT * HDIM / 4;
    conv_kernel<<<(n4 + CT - 1) / CT, CT>>>(x, xh, xl, n4);
    n4 = NE * IDIM * HDIM / 4;
    conv_kernel<<<(n4 + CT - 1) / CT, CT>>>(w_gate, wgh, wgl, n4);
    conv_kernel<<<(n4 + CT - 1) / CT, CT>>>(w_up, wuh, wul, n4);
    conv_kernel<<<(n4 + CT - 1) / CT, CT>>>(w_down, wdh, wdl, n4);
    n4 = IDIM * HDIM / 4;
    conv_kernel<<<(n4 + CT - 1) / CT, CT>>>(ws_gate, sgh, sgl, n4);
    conv_kernel<<<(n4 + CT - 1) / CT, CT>>>(ws_up, suh, sul, n4);
    conv_kernel<<<(n4 + CT - 1) / CT, CT>>>(ws_down, sdh, sdl, n4);

    gate_kernel<<<NT / 8, 256>>>(x, gate_w);
    scan_kernel<<<1, 32>>>();
    scatter_kernel<<<(NROUTED + 255) / 256, 256>>>();

    gateup_mma<<<dim3((IDIM + 127) / 128, MAXTILES + NT / 128, 1), 256, GU_SMEM>>>();
    down_mma<<<dim3(HDIM / 128, MAXTILES + NT / 128, 1), 256, DN_SMEM>>>();
    combine_kernel<<<(NT * (HDIM / 4) + 255) / 256, 256>>>(out);
}

// round 5
// speedup vs baseline: 3.3829x; 1.4768x over previous
#include <cuda_runtime.h>
#include <cuda_fp16.h>
#include <math.h>
#include <stdint.h>

#define HDIM 1024
#define IDIM 2752
#define NE   8
#define NT   4096
#define NROUTED (2*NT)
#define NRP  9216
#define SHB  9216
#define NEP  (NRP + NT)
#define MAXTILES 72

// ---------------- scratch ----------------
__device__ int   g_counts[NE];
__device__ int   g_offp[NE];
__device__ int   g_cursor[NE];
__device__ int   g_tile_e[MAXTILES];
__device__ int   g_tile_m[MAXTILES];
__device__ int   g_topk_idx[NROUTED];
__device__ float g_topk_w[NROUTED];
__device__ int   g_perm[NRP];
__device__ float g_wgt[NRP];
__device__ int   g_entry_of[NROUTED];

__device__ __half g_xh[(size_t)NT * HDIM];
__device__ __half g_xl[(size_t)NT * HDIM];
__device__ __half g_wg[(size_t)NE * IDIM * HDIM];
__device__ __half g_wu[(size_t)NE * IDIM * HDIM];
__device__ __half g_wd[(size_t)NE * HDIM * IDIM];
__device__ __half g_sg[(size_t)IDIM * HDIM];
__device__ __half g_su[(size_t)IDIM * HDIM];
__device__ __half g_sd[(size_t)HDIM * IDIM];
__device__ __half g_hmh[(size_t)NEP * IDIM];
__device__ __half g_hml[(size_t)NEP * IDIM];
__device__ float  g_eo[(size_t)NEP * HDIM];

// ---------------- helpers ----------------
__device__ __forceinline__ uint32_t smem_u32(const void* p) {
    uint32_t a;
    asm("{ .reg .u64 t; cvta.to.shared.u64 t, %1; cvt.u32.u64 %0, t; }"
        : "=r"(a) : "l"(p));
    return a;
}
__device__ __forceinline__ void ldsm4(uint32_t* r, uint32_t a) {
    asm volatile("ldmatrix.sync.aligned.m8n8.x4.shared.b16 {%0,%1,%2,%3}, [%4];"
                 : "=r"(r[0]), "=r"(r[1]), "=r"(r[2]), "=r"(r[3]) : "r"(a));
}
__device__ __forceinline__ void mma16816(float* c, const uint32_t* a,
                                         uint32_t b0, uint32_t b1) {
    asm volatile(
        "mma.sync.aligned.m16n8k16.row.col.f32.f16.f16.f32 "
        "{%0,%1,%2,%3}, {%4,%5,%6,%7}, {%8,%9}, {%0,%1,%2,%3};"
        : "+f"(c[0]), "+f"(c[1]), "+f"(c[2]), "+f"(c[3])
        : "r"(a[0]), "r"(a[1]), "r"(a[2]), "r"(a[3]), "r"(b0), "r"(b1));
}
__device__ __forceinline__ void cpasync16(uint32_t dst, const void* src) {
    asm volatile("cp.async.cg.shared.global [%0], [%1], 16;" :: "r"(dst), "l"(src));
}
#define CP_COMMIT() asm volatile("cp.async.commit_group;" ::: "memory")
#define CP_WAIT1()  asm volatile("cp.async.wait_group 1;" ::: "memory")
#define CP_WAIT0()  asm volatile("cp.async.wait_group 0;" ::: "memory")

__device__ __forceinline__ uint32_t pack2h(__half a, __half b) {
    return ((uint32_t)__half_as_ushort(b) << 16) | __half_as_ushort(a);
}
__device__ __forceinline__ uint32_t pack_hilo(float a, float b, uint32_t& lo) {
    __half ha = __float2half_rn(a), hb = __float2half_rn(b);
    __half la = __float2half_rn(a - __half2float(ha));
    __half lb = __float2half_rn(b - __half2float(hb));
    lo = pack2h(la, lb);
    return pack2h(ha, hb);
}

// ---------------- small kernels ----------------
__global__ void init_kernel() {
    int i = threadIdx.x;
    if (i < NE) g_counts[i] = 0;
}

// x -> fp16 hi/lo
__global__ void conv_hl_kernel(const float* __restrict__ src,
                               __half* __restrict__ h,
                               __half* __restrict__ l, int n4) {
    int i = blockIdx.x * blockDim.x + threadIdx.x;
    if (i >= n4) return;
    float4 v = ((const float4*)src)[i];
    uint32_t l0, l1;
    uint32_t h0 = pack_hilo(v.x, v.y, l0);
    uint32_t h1 = pack_hilo(v.z, v.w, l1);
    uint2 ph, pl;
    ph.x = h0; ph.y = h1;
    pl.x = l0; pl.y = l1;
    ((uint2*)h)[i] = ph;
    ((uint2*)l)[i] = pl;
}

// weights -> single fp16
__global__ void conv_f16_kernel(const float* __restrict__ src,
                                __half* __restrict__ h, int n4) {
    int i = blockIdx.x * blockDim.x + threadIdx.x;
    if (i >= n4) return;
    float4 v = ((const float4*)src)[i];
    uint2 ph;
    ph.x = pack2h(__float2half_rn(v.x), __float2half_rn(v.y));
    ph.y = pack2h(__float2half_rn(v.z), __float2half_rn(v.w));
    ((uint2*)h)[i] = ph;
}

__global__ void gate_kernel(const float* __restrict__ x,
                            const float* __restrict__ gw) {
    int warp = (blockIdx.x * blockDim.x + threadIdx.x) >> 5;
    int lane = threadIdx.x & 31;
    if (warp >= NT) return;
    const float4* x4 = (const float4*)(x + (size_t)warp * HDIM);
    const float4* gw4 = (const float4*)gw;
    float acc[NE];
#pragma unroll
    for (int e = 0; e < NE; e++) acc[e] = 0.f;
    for (int h4 = lane; h4 < HDIM / 4; h4 += 32) {
        float4 xv = x4[h4];
#pragma unroll
        for (int e = 0; e < NE; e++) {
            float4 g = gw4[e * (HDIM / 4) + h4];
            acc[e] += xv.x * g.x + xv.y * g.y + xv.z * g.z + xv.w * g.w;
        }
    }
#pragma unroll
    for (int e = 0; e < NE; e++)
#pragma unroll
        for (int off = 16; off > 0; off >>= 1)
            acc[e] += __shfl_down_sync(0xffffffffu, acc[e], off);
    if (lane == 0) {
        float mx = acc[0];
#pragma unroll
        for (int e = 1; e < NE; e++) mx = fmaxf(mx, acc[e]);
        float p[NE], s = 0.f;
#pragma unroll
        for (int e = 0; e < NE; e++) { p[e] = expf(acc[e] - mx); s += p[e]; }
        float inv = 1.f / s;
#pragma unroll
        for (int e = 0; e < NE; e++) p[e] *= inv;
        int i1 = 0; float p1 = p[0];
#pragma unroll
        for (int e = 1; e < NE; e++) if (p[e] > p1) { p1 = p[e]; i1 = e; }
        int i2 = -1; float p2 = -1.f;
#pragma unroll
        for (int e = 0; e < NE; e++) {
            if (e == i1) continue;
            if (p[e] > p2) { p2 = p[e]; i2 = e; }
        }
        float rn = 1.f / (p1 + p2 + 1e-20f);
        g_topk_idx[2 * warp + 0] = i1;
        g_topk_idx[2 * warp + 1] = i2;
        g_topk_w[2 * warp + 0] = p1 * rn;
        g_topk_w[2 * warp + 1] = p2 * rn;
        atomicAdd(&g_counts[i1], 1);
        atomicAdd(&g_counts[i2], 1);
    }
}

__global__ void scan_kernel() {
    if (threadIdx.x == 0) {
        int s = 0, t = 0;
        for (int e = 0; e < NE; e++) {
            g_offp[e] = s;
            g_cursor[e] = s;
            int c = g_counts[e];
            int nt = (c + 127) >> 7;
            for (int m = 0; m < nt; m++) { g_tile_e[t] = e; g_tile_m[t] = m << 7; t++; }
            s += (c + 127) & ~127;
        }
        for (; t < MAXTILES; t++) g_tile_e[t] = -1;
    }
}

__global__ void scatter_kernel() {
    int i = blockIdx.x * blockDim.x + threadIdx.x;
    if (i >= NROUTED) return;
    int t = i >> 1;
    int e = g_topk_idx[i];
    int pos = atomicAdd(&g_cursor[e], 1);
    g_perm[pos] = t;
    g_wgt[pos] = g_topk_w[i];
    g_entry_of[i] = pos;
}

// ---------------- gate+up MMA GEMM ----------------
// block 128x128 (x2 outputs), 8 warps (64x32 warp tiles), BK=64
// A (activations) fp16 hi/lo 2-pass, weights single fp16
#define GU_PART  16384
#define GU_STAGE (4 * GU_PART)   // Ah, Al, G, U
#define GU_SMEM  (2 * GU_STAGE)  // 128KB

__global__ __launch_bounds__(256, 1) void gateup_mma() {
    extern __shared__ char sm[];
    uint32_t sb = smem_u32(sm);
    int tid = threadIdx.x, wid = tid >> 5, lane = tid & 31;

    int y = blockIdx.y;
    int e, m0, base;
    bool is_shared;
    if (y >= MAXTILES) {
        is_shared = true; m0 = (y - MAXTILES) << 7; base = SHB;
    } else {
        e = g_tile_e[y];
        if (e < 0) return;
        is_shared = false; m0 = g_tile_m[y]; base = g_offp[e];
    }
    int n0 = blockIdx.x * 128;

    const __half* WG = is_shared ? g_sg : g_wg + (size_t)e * IDIM * HDIM;
    const __half* WU = is_shared ? g_su : g_wu + (size_t)e * IDIM * HDIM;

    int lrow = tid >> 1, kb0 = (tid & 1) * 4;
    uint32_t swo[4];
#pragma unroll
    for (int j = 0; j < 4; j++)
        swo[j] = lrow * 128 + (((kb0 + j) ^ (lrow & 7)) << 4);
    int tok = is_shared ? (m0 + lrow) : g_perm[base + m0 + lrow];
    const __half* pAh = g_xh + (size_t)tok * HDIM + kb0 * 8;
    const __half* pAl = g_xl + (size_t)tok * HDIM + kb0 * 8;
    int nr = n0 + lrow; if (nr > IDIM - 1) nr = IDIM - 1;
    const __half* pG = WG + (size_t)nr * HDIM + kb0 * 8;
    const __half* pU = WU + (size_t)nr * HDIM + kb0 * 8;

    auto issue = [&](int s) {
        int k0 = s * 64;
        uint32_t bb = sb + (s & 1) * GU_STAGE;
#pragma unroll
        for (int j = 0; j < 4; j++) {
            cpasync16(bb + 0 * GU_PART + swo[j], pAh + k0 + j * 8);
            cpasync16(bb + 1 * GU_PART + swo[j], pAl + k0 + j * 8);
            cpasync16(bb + 2 * GU_PART + swo[j], pG + k0 + j * 8);
            cpasync16(bb + 3 * GU_PART + swo[j], pU + k0 + j * 8);
        }
    };

    int warpM = (wid & 1) * 64;
    int warpN = (wid >> 1) * 32;
    int la = lane & 15, kh = lane >> 4, x7 = la & 7;
    uint32_t rowA[4], rowB[2];
#pragma unroll
    for (int mf = 0; mf < 4; mf++) rowA[mf] = (warpM + mf * 16 + la) * 128;
#pragma unroll
    for (int s2 = 0; s2 < 2; s2++) rowB[s2] = (warpN + s2 * 16 + la) * 128;

    float aG[4][4][4], aU[4][4][4];
#pragma unroll
    for (int mf = 0; mf < 4; mf++)
#pragma unroll
        for (int nf = 0; nf < 4; nf++)
#pragma unroll
            for (int q = 0; q < 4; q++) { aG[mf][nf][q] = 0.f; aU[mf][nf][q] = 0.f; }

    issue(0); CP_COMMIT();
    for (int s = 0; s < 16; s++) {
        if (s < 15) { issue(s + 1); CP_COMMIT(); CP_WAIT1(); }
        else CP_WAIT0();
        __syncthreads();
        uint32_t bb = sb + (s & 1) * GU_STAGE;
#pragma unroll
        for (int k16 = 0; k16 < 4; k16++) {
            uint32_t ko = (uint32_t)(((k16 * 2 + kh) ^ x7) << 4);
            uint32_t Ah[4][4], Al[4][4];
#pragma unroll
            for (int mf = 0; mf < 4; mf++) {
                ldsm4(Ah[mf], bb + 0 * GU_PART + rowA[mf] + ko);
                ldsm4(Al[mf], bb + 1 * GU_PART + rowA[mf] + ko);
            }
            uint32_t G[2][4], U[2][4];
#pragma unroll
            for (int s2 = 0; s2 < 2; s2++) {
                ldsm4(G[s2], bb + 2 * GU_PART + rowB[s2] + ko);
                ldsm4(U[s2], bb + 3 * GU_PART + rowB[s2] + ko);
            }
#pragma unroll
            for (int mf = 0; mf < 4; mf++)
#pragma unroll
                for (int s2 = 0; s2 < 2; s2++)
#pragma unroll
                    for (int j = 0; j < 2; j++) {
                        int nf = s2 * 2 + j;
                        mma16816(aG[mf][nf], Ah[mf], G[s2][j], G[s2][2 + j]);
                        mma16816(aG[mf][nf], Al[mf], G[s2][j], G[s2][2 + j]);
                        mma16816(aU[mf][nf], Ah[mf], U[s2][j], U[s2][2 + j]);
                        mma16816(aU[mf][nf], Al[mf], U[s2][j], U[s2][2 + j]);
                    }
        }
        __syncthreads();
    }

    // epilogue: hmid = silu(g)*u, fp16 hi/lo
    int qr = lane >> 2, qc = (lane & 3) * 2;
#pragma unroll
    for (int mf = 0; mf < 4; mf++)
#pragma unroll
        for (int nf = 0; nf < 4; nf++) {
            int col = n0 + warpN + nf * 8 + qc;
            if (col >= IDIM) continue;
            float* cg = aG[mf][nf];
            float* cu = aU[mf][nf];
            int r0 = m0 + warpM + mf * 16 + qr;
            float g0 = cg[0], g1 = cg[1], g2 = cg[2], g3 = cg[3];
            float v00 = (g0 / (1.f + expf(-g0))) * cu[0];
            float v01 = (g1 / (1.f + expf(-g1))) * cu[1];
            float v10 = (g2 / (1.f + expf(-g2))) * cu[2];
            float v11 = (g3 / (1.f + expf(-g3))) * cu[3];
            uint32_t lo0, lo1;
            uint32_t hi0 = pack_hilo(v00, v01, lo0);
            uint32_t hi1 = pack_hilo(v10, v11, lo1);
            size_t o0 = (size_t)(base + r0) * IDIM + col;
            size_t o1 = o0 + (size_t)8 * IDIM;
            *(uint32_t*)(g_hmh + o0) = hi0;
            *(uint32_t*)(g_hml + o0) = lo0;
            *(uint32_t*)(g_hmh + o1) = hi1;
            *(uint32_t*)(g_hml + o1) = lo1;
        }
}

// ---------------- down MMA GEMM ----------------
#define DN_PART  16384
#define DN_STAGE (3 * DN_PART)   // Ah, Al, B
#define DN_SMEM  (2 * DN_STAGE)  // 96KB

__global__ __launch_bounds__(256, 1) void down_mma() {
    extern __shared__ char sm[];
    uint32_t sb = smem_u32(sm);
    int tid = threadIdx.x, wid = tid >> 5, lane = tid & 31;

    int y = blockIdx.y;
    int e, m0, base;
    bool is_shared;
    if (y >= MAXTILES) {
        is_shared = true; m0 = (y - MAXTILES) << 7; base = SHB;
    } else {
        e = g_tile_e[y];
        if (e < 0) return;
        is_shared = false; m0 = g_tile_m[y]; base = g_offp[e];
    }
    int n0 = blockIdx.x * 128;

    const __half* WD = is_shared ? g_sd : g_wd + (size_t)e * HDIM * IDIM;

    int lrow = tid >> 1, kb0 = (tid & 1) * 4;
    uint32_t swo[4];
#pragma unroll
    for (int j = 0; j < 4; j++)
        swo[j] = lrow * 128 + (((kb0 + j) ^ (lrow & 7)) << 4);
    const __half* pAh = g_hmh + (size_t)(base + m0 + lrow) * IDIM + kb0 * 8;
    const __half* pAl = g_hml + (size_t)(base + m0 + lrow) * IDIM + kb0 * 8;
    const __half* pB = WD + (size_t)(n0 + lrow) * IDIM + kb0 * 8;

    auto issue = [&](int s) {
        int k0 = s * 64;
        uint32_t bb = sb + (s & 1) * DN_STAGE;
#pragma unroll
        for (int j = 0; j < 4; j++) {
            cpasync16(bb + 0 * DN_PART + swo[j], pAh + k0 + j * 8);
            cpasync16(bb + 1 * DN_PART + swo[j], pAl + k0 + j * 8);
            cpasync16(bb + 2 * DN_PART + swo[j], pB + k0 + j * 8);
        }
    };

    int warpM = (wid & 1) * 64;
    int warpN = (wid >> 1) * 32;
    int la = lane & 15, kh = lane >> 4, x7 = la & 7;
    uint32_t rowA[4], rowB[2];
#pragma unroll
    for (int mf = 0; mf < 4; mf++) rowA[mf] = (warpM + mf * 16 + la) * 128;
#pragma unroll
    for (int s2 = 0; s2 < 2; s2++) rowB[s2] = (warpN + s2 * 16 + la) * 128;

    float acc[4][4][4];
#pragma unroll
    for (int mf = 0; mf < 4; mf++)
#pragma unroll
        for (int nf = 0; nf < 4; nf++)
#pragma unroll
            for (int q = 0; q < 4; q++) acc[mf][nf][q] = 0.f;

    const int S = IDIM / 64;   // 43
    issue(0); CP_COMMIT();
    for (int s = 0; s < S; s++) {
        if (s < S - 1) { issue(s + 1); CP_COMMIT(); CP_WAIT1(); }
        else CP_WAIT0();
        __syncthreads();
        uint32_t bb = sb + (s & 1) * DN_STAGE;
#pragma unroll
        for (int k16 = 0; k16 < 4; k16++) {
            uint32_t ko = (uint32_t)(((k16 * 2 + kh) ^ x7) << 4);
            uint32_t Ah[4][4], Al[4][4];
#pragma unroll
            for (int mf = 0; mf < 4; mf++) {
                ldsm4(Ah[mf], bb + 0 * DN_PART + rowA[mf] + ko);
                ldsm4(Al[mf], bb + 1 * DN_PART + rowA[mf] + ko);
            }
            uint32_t B[2][4];
#pragma unroll
            for (int s2 = 0; s2 < 2; s2++)
                ldsm4(B[s2], bb + 2 * DN_PART + rowB[s2] + ko);
#pragma unroll
            for (int mf = 0; mf < 4; mf++)
#pragma unroll
                for (int s2 = 0; s2 < 2; s2++)
#pragma unroll
                    for (int j = 0; j < 2; j++) {
                        int nf = s2 * 2 + j;
                        mma16816(acc[mf][nf], Ah[mf], B[s2][j], B[s2][2 + j]);
                        mma16816(acc[mf][nf], Al[mf], B[s2][j], B[s2][2 + j]);
                    }
        }
        __syncthreads();
    }

    int qr = lane >> 2, qc = (lane & 3) * 2;
#pragma unroll
    for (int mf = 0; mf < 4; mf++) {
        int r0 = m0 + warpM + mf * 16 + qr;
        float w0 = is_shared ? 1.f : g_wgt[base + r0];
        float w1 = is_shared ? 1.f : g_wgt[base + r0 + 8];
#pragma unroll
        for (int nf = 0; nf < 4; nf++) {
            int col = n0 + warpN + nf * 8 + qc;
            float* c = acc[mf][nf];
            size_t o0 = (size_t)(base + r0) * HDIM + col;
            size_t o1 = o0 + (size_t)8 * HDIM;
            float2 v0 = make_float2(c[0] * w0, c[1] * w0);
            float2 v1 = make_float2(c[2] * w1, c[3] * w1);
            *(float2*)(g_eo + o0) = v0;
            *(float2*)(g_eo + o1) = v1;
        }
    }
}

// ---------------- combine ----------------
__global__ void combine_kernel(float* __restrict__ out) {
    int idx = blockIdx.x * blockDim.x + threadIdx.x;
    const int HC = HDIM / 4;
    if (idx >= NT * HC) return;
    int t = idx / HC;
    int c = idx - t * HC;
    const float4* eo4 = (const float4*)g_eo;
    int e1 = g_entry_of[2 * t + 0];
    int e2 = g_entry_of[2 * t + 1];
    float4 a = eo4[(size_t)e1 * HC + c];
    float4 b = eo4[(size_t)e2 * HC + c];
    float4 s = eo4[(size_t)(SHB + t) * HC + c];
    float4 r;
    r.x = a.x + b.x + s.x;
    r.y = a.y + b.y + s.y;
    r.z = a.z + b.z + s.z;
    r.w = a.w + b.w + s.w;
    ((float4*)out)[idx] = r;
}

// ---------------- launch ----------------
extern "C" void kernel_launch(void* const* d_in, const int* in_sizes, int n_in,
                              void* d_out, int out_size) {
    const float* x       = (const float*)d_in[0];
    const float* gate_w  = (const float*)d_in[1];
    const float* w_gate  = (const float*)d_in[2];
    const float* w_up    = (const float*)d_in[3];
    const float* w_down  = (const float*)d_in[4];
    const float* ws_gate = (const float*)d_in[5];
    const float* ws_up   = (const float*)d_in[6];
    const float* ws_down = (const float*)d_in[7];
    float* out = (float*)d_out;

    cudaFuncSetAttribute(gateup_mma, cudaFuncAttributeMaxDynamicSharedMemorySize, GU_SMEM);
    cudaFuncSetAttribute(down_mma,   cudaFuncAttributeMaxDynamicSharedMemorySize, DN_SMEM);

    __half *xh, *xl, *wg, *wu, *wd, *sg, *su, *sd;
    cudaGetSymbolAddress((void**)&xh, g_xh); cudaGetSymbolAddress((void**)&xl, g_xl);
    cudaGetSymbolAddress((void**)&wg, g_wg); cudaGetSymbolAddress((void**)&wu, g_wu);
    cudaGetSymbolAddress((void**)&wd, g_wd);
    cudaGetSymbolAddress((void**)&sg, g_sg); cudaGetSymbolAddress((void**)&su, g_su);
    cudaGetSymbolAddress((void**)&sd, g_sd);

    init_kernel<<<1, 32>>>();
    const int CT = 256;
    int n4;
    n4 = NT * HDIM / 4;
    conv_hl_kernel<<<(n4 + CT - 1) / CT, CT>>>(x, xh, xl, n4);
    n4 = NE * IDIM * HDIM / 4;
    conv_f16_kernel<<<(n4 + CT - 1) / CT, CT>>>(w_gate, wg, n4);
    conv_f16_kernel<<<(n4 + CT - 1) / CT, CT>>>(w_up, wu, n4);
    conv_f16_kernel<<<(n4 + CT - 1) / CT, CT>>>(w_down, wd, n4);
    n4 = IDIM * HDIM / 4;
    conv_f16_kernel<<<(n4 + CT - 1) / CT, CT>>>(ws_gate, sg, n4);
    conv_f16_kernel<<<(n4 + CT - 1) / CT, CT>>>(ws_up, su, n4);
    conv_f16_kernel<<<(n4 + CT - 1) / CT, CT>>>(ws_down, sd, n4);

    gate_kernel<<<NT / 8, 256>>>(x, gate_w);
    scan_kernel<<<1, 32>>>();
    scatter_kernel<<<(NROUTED + 255) / 256, 256>>>();

    gateup_mma<<<dim3((IDIM + 127) / 128, MAXTILES + NT / 128, 1), 256, GU_SMEM>>>();
    down_mma<<<dim3(HDIM / 128, MAXTILES + NT / 128, 1), 256, DN_SMEM>>>();
    combine_kernel<<<(NT * (HDIM / 4) + 255) / 256, 256>>>(out);
}

// round 6
// speedup vs baseline: 5.4648x; 1.6154x over previous
#include <cuda_runtime.h>
#include <cuda_fp16.h>
#include <math.h>
#include <stdint.h>

#define HDIM 1024
#define IDIM 2752
#define NE   8
#define NT   4096
#define NROUTED (2*NT)
#define NRP  9216
#define SHB  9216
#define NEP  (NRP + NT)
#define MAXTILES 72

// ---------------- scratch ----------------
__device__ int   g_counts[NE];
__device__ int   g_offp[NE];
__device__ int   g_cursor[NE];
__device__ int   g_tile_e[MAXTILES];
__device__ int   g_tile_m[MAXTILES];
__device__ int   g_topk_idx[NROUTED];
__device__ float g_topk_w[NROUTED];
__device__ int   g_perm[NRP];
__device__ float g_wgt[NRP];
__device__ int   g_entry_of[NROUTED];

__device__ __half g_x16[(size_t)NT * HDIM];
__device__ __half g_wg[(size_t)NE * IDIM * HDIM];
__device__ __half g_wu[(size_t)NE * IDIM * HDIM];
__device__ __half g_wd[(size_t)NE * HDIM * IDIM];
__device__ __half g_sg[(size_t)IDIM * HDIM];
__device__ __half g_su[(size_t)IDIM * HDIM];
__device__ __half g_sd[(size_t)HDIM * IDIM];
__device__ __half g_hm[(size_t)NEP * IDIM];
__device__ float  g_eo[(size_t)NEP * HDIM];

// ---------------- helpers ----------------
__device__ __forceinline__ uint32_t smem_u32(const void* p) {
    uint32_t a;
    asm("{ .reg .u64 t; cvta.to.shared.u64 t, %1; cvt.u32.u64 %0, t; }"
        : "=r"(a) : "l"(p));
    return a;
}
__device__ __forceinline__ void ldsm4(uint32_t* r, uint32_t a) {
    asm volatile("ldmatrix.sync.aligned.m8n8.x4.shared.b16 {%0,%1,%2,%3}, [%4];"
                 : "=r"(r[0]), "=r"(r[1]), "=r"(r[2]), "=r"(r[3]) : "r"(a));
}
__device__ __forceinline__ void mma16816(float* c, const uint32_t* a,
                                         uint32_t b0, uint32_t b1) {
    asm volatile(
        "mma.sync.aligned.m16n8k16.row.col.f32.f16.f16.f32 "
        "{%0,%1,%2,%3}, {%4,%5,%6,%7}, {%8,%9}, {%0,%1,%2,%3};"
        : "+f"(c[0]), "+f"(c[1]), "+f"(c[2]), "+f"(c[3])
        : "r"(a[0]), "r"(a[1]), "r"(a[2]), "r"(a[3]), "r"(b0), "r"(b1));
}
__device__ __forceinline__ void cpasync16(uint32_t dst, const void* src) {
    asm volatile("cp.async.cg.shared.global [%0], [%1], 16;" :: "r"(dst), "l"(src));
}
#define CP_COMMIT() asm volatile("cp.async.commit_group;" ::: "memory")
#define CP_WAIT1()  asm volatile("cp.async.wait_group 1;" ::: "memory")
#define CP_WAIT0()  asm volatile("cp.async.wait_group 0;" ::: "memory")

__device__ __forceinline__ uint32_t pack2h(__half a, __half b) {
    return ((uint32_t)__half_as_ushort(b) << 16) | __half_as_ushort(a);
}

// ---------------- small kernels ----------------
__global__ void init_kernel() {
    int i = threadIdx.x;
    if (i < NE) g_counts[i] = 0;
}

// float -> fp16
__global__ void conv_f16_kernel(const float* __restrict__ src,
                                __half* __restrict__ h, int n4) {
    int i = blockIdx.x * blockDim.x + threadIdx.x;
    if (i >= n4) return;
    float4 v = ((const float4*)src)[i];
    uint2 ph;
    ph.x = pack2h(__float2half_rn(v.x), __float2half_rn(v.y));
    ph.y = pack2h(__float2half_rn(v.z), __float2half_rn(v.w));
    ((uint2*)h)[i] = ph;
}

__global__ void gate_kernel(const float* __restrict__ x,
                            const float* __restrict__ gw) {
    int warp = (blockIdx.x * blockDim.x + threadIdx.x) >> 5;
    int lane = threadIdx.x & 31;
    if (warp >= NT) return;
    const float4* x4 = (const float4*)(x + (size_t)warp * HDIM);
    const float4* gw4 = (const float4*)gw;
    float acc[NE];
#pragma unroll
    for (int e = 0; e < NE; e++) acc[e] = 0.f;
    for (int h4 = lane; h4 < HDIM / 4; h4 += 32) {
        float4 xv = x4[h4];
#pragma unroll
        for (int e = 0; e < NE; e++) {
            float4 g = gw4[e * (HDIM / 4) + h4];
            acc[e] += xv.x * g.x + xv.y * g.y + xv.z * g.z + xv.w * g.w;
        }
    }
#pragma unroll
    for (int e = 0; e < NE; e++)
#pragma unroll
        for (int off = 16; off > 0; off >>= 1)
            acc[e] += __shfl_down_sync(0xffffffffu, acc[e], off);
    if (lane == 0) {
        float mx = acc[0];
#pragma unroll
        for (int e = 1; e < NE; e++) mx = fmaxf(mx, acc[e]);
        float p[NE], s = 0.f;
#pragma unroll
        for (int e = 0; e < NE; e++) { p[e] = expf(acc[e] - mx); s += p[e]; }
        float inv = 1.f / s;
#pragma unroll
        for (int e = 0; e < NE; e++) p[e] *= inv;
        int i1 = 0; float p1 = p[0];
#pragma unroll
        for (int e = 1; e < NE; e++) if (p[e] > p1) { p1 = p[e]; i1 = e; }
        int i2 = -1; float p2 = -1.f;
#pragma unroll
        for (int e = 0; e < NE; e++) {
            if (e == i1) continue;
            if (p[e] > p2) { p2 = p[e]; i2 = e; }
        }
        float rn = 1.f / (p1 + p2 + 1e-20f);
        g_topk_idx[2 * warp + 0] = i1;
        g_topk_idx[2 * warp + 1] = i2;
        g_topk_w[2 * warp + 0] = p1 * rn;
        g_topk_w[2 * warp + 1] = p2 * rn;
        atomicAdd(&g_counts[i1], 1);
        atomicAdd(&g_counts[i2], 1);
    }
}

__global__ void scan_kernel() {
    if (threadIdx.x == 0) {
        int s = 0, t = 0;
        for (int e = 0; e < NE; e++) {
            g_offp[e] = s;
            g_cursor[e] = s;
            int c = g_counts[e];
            int nt = (c + 127) >> 7;
            for (int m = 0; m < nt; m++) { g_tile_e[t] = e; g_tile_m[t] = m << 7; t++; }
            s += (c + 127) & ~127;
        }
        for (; t < MAXTILES; t++) g_tile_e[t] = -1;
    }
}

__global__ void scatter_kernel() {
    int i = blockIdx.x * blockDim.x + threadIdx.x;
    if (i >= NROUTED) return;
    int t = i >> 1;
    int e = g_topk_idx[i];
    int pos = atomicAdd(&g_cursor[e], 1);
    g_perm[pos] = t;
    g_wgt[pos] = g_topk_w[i];
    g_entry_of[i] = pos;
}

// ---------------- gate+up MMA GEMM ----------------
// block 128x128 (x2 outputs), 8 warps (64x32 warp tiles), BK=64, single-pass fp16
#define GU_PART  16384
#define GU_STAGE (3 * GU_PART)   // A, G, U
#define GU_SMEM  (2 * GU_STAGE)  // 96KB

__global__ __launch_bounds__(256, 1) void gateup_mma() {
    extern __shared__ char sm[];
    uint32_t sb = smem_u32(sm);
    int tid = threadIdx.x, wid = tid >> 5, lane = tid & 31;

    int y = blockIdx.y;
    int e, m0, base;
    bool is_shared;
    if (y >= MAXTILES) {
        is_shared = true; m0 = (y - MAXTILES) << 7; base = SHB;
    } else {
        e = g_tile_e[y];
        if (e < 0) return;
        is_shared = false; m0 = g_tile_m[y]; base = g_offp[e];
    }
    int n0 = blockIdx.x * 128;

    const __half* WG = is_shared ? g_sg : g_wg + (size_t)e * IDIM * HDIM;
    const __half* WU = is_shared ? g_su : g_wu + (size_t)e * IDIM * HDIM;

    int lrow = tid >> 1, kb0 = (tid & 1) * 4;
    uint32_t swo[4];
#pragma unroll
    for (int j = 0; j < 4; j++)
        swo[j] = lrow * 128 + (((kb0 + j) ^ (lrow & 7)) << 4);
    int tok = is_shared ? (m0 + lrow) : g_perm[base + m0 + lrow];
    const __half* pA = g_x16 + (size_t)tok * HDIM + kb0 * 8;
    int nr = n0 + lrow; if (nr > IDIM - 1) nr = IDIM - 1;
    const __half* pG = WG + (size_t)nr * HDIM + kb0 * 8;
    const __half* pU = WU + (size_t)nr * HDIM + kb0 * 8;

    auto issue = [&](int s) {
        int k0 = s * 64;
        uint32_t bb = sb + (s & 1) * GU_STAGE;
#pragma unroll
        for (int j = 0; j < 4; j++) {
            cpasync16(bb + 0 * GU_PART + swo[j], pA + k0 + j * 8);
            cpasync16(bb + 1 * GU_PART + swo[j], pG + k0 + j * 8);
            cpasync16(bb + 2 * GU_PART + swo[j], pU + k0 + j * 8);
        }
    };

    int warpM = (wid & 1) * 64;
    int warpN = (wid >> 1) * 32;
    int la = lane & 15, kh = lane >> 4, x7 = la & 7;
    uint32_t rowA[4], rowB[2];
#pragma unroll
    for (int mf = 0; mf < 4; mf++) rowA[mf] = (warpM + mf * 16 + la) * 128;
#pragma unroll
    for (int s2 = 0; s2 < 2; s2++) rowB[s2] = (warpN + s2 * 16 + la) * 128;

    float aG[4][4][4], aU[4][4][4];
#pragma unroll
    for (int mf = 0; mf < 4; mf++)
#pragma unroll
        for (int nf = 0; nf < 4; nf++)
#pragma unroll
            for (int q = 0; q < 4; q++) { aG[mf][nf][q] = 0.f; aU[mf][nf][q] = 0.f; }

    issue(0); CP_COMMIT();
    for (int s = 0; s < 16; s++) {
        if (s < 15) { issue(s + 1); CP_COMMIT(); CP_WAIT1(); }
        else CP_WAIT0();
        __syncthreads();
        uint32_t bb = sb + (s & 1) * GU_STAGE;
#pragma unroll
        for (int k16 = 0; k16 < 4; k16++) {
            uint32_t ko = (uint32_t)(((k16 * 2 + kh) ^ x7) << 4);
            uint32_t A[4][4];
#pragma unroll
            for (int mf = 0; mf < 4; mf++)
                ldsm4(A[mf], bb + 0 * GU_PART + rowA[mf] + ko);
            uint32_t G[2][4], U[2][4];
#pragma unroll
            for (int s2 = 0; s2 < 2; s2++) {
                ldsm4(G[s2], bb + 1 * GU_PART + rowB[s2] + ko);
                ldsm4(U[s2], bb + 2 * GU_PART + rowB[s2] + ko);
            }
#pragma unroll
            for (int mf = 0; mf < 4; mf++)
#pragma unroll
                for (int s2 = 0; s2 < 2; s2++)
#pragma unroll
                    for (int j = 0; j < 2; j++) {
                        int nf = s2 * 2 + j;
                        mma16816(aG[mf][nf], A[mf], G[s2][j], G[s2][2 + j]);
                        mma16816(aU[mf][nf], A[mf], U[s2][j], U[s2][2 + j]);
                    }
        }
        __syncthreads();
    }

    // epilogue: hmid = silu(g)*u -> fp16
    int qr = lane >> 2, qc = (lane & 3) * 2;
#pragma unroll
    for (int mf = 0; mf < 4; mf++)
#pragma unroll
        for (int nf = 0; nf < 4; nf++) {
            int col = n0 + warpN + nf * 8 + qc;
            if (col >= IDIM) continue;
            float* cg = aG[mf][nf];
            float* cu = aU[mf][nf];
            int r0 = m0 + warpM + mf * 16 + qr;
            float g0 = cg[0], g1 = cg[1], g2 = cg[2], g3 = cg[3];
            float v00 = (g0 / (1.f + expf(-g0))) * cu[0];
            float v01 = (g1 / (1.f + expf(-g1))) * cu[1];
            float v10 = (g2 / (1.f + expf(-g2))) * cu[2];
            float v11 = (g3 / (1.f + expf(-g3))) * cu[3];
            uint32_t p0 = pack2h(__float2half_rn(v00), __float2half_rn(v01));
            uint32_t p1 = pack2h(__float2half_rn(v10), __float2half_rn(v11));
            size_t o0 = (size_t)(base + r0) * IDIM + col;
            size_t o1 = o0 + (size_t)8 * IDIM;
            *(uint32_t*)(g_hm + o0) = p0;
            *(uint32_t*)(g_hm + o1) = p1;
        }
}

// ---------------- down MMA GEMM ----------------
#define DN_PART  16384
#define DN_STAGE (2 * DN_PART)   // A, B
#define DN_SMEM  (2 * DN_STAGE)  // 64KB

__global__ __launch_bounds__(256, 1) void down_mma() {
    extern __shared__ char sm[];
    uint32_t sb = smem_u32(sm);
    int tid = threadIdx.x, wid = tid >> 5, lane = tid & 31;

    int y = blockIdx.y;
    int e, m0, base;
    bool is_shared;
    if (y >= MAXTILES) {
        is_shared = true; m0 = (y - MAXTILES) << 7; base = SHB;
    } else {
        e = g_tile_e[y];
        if (e < 0) return;
        is_shared = false; m0 = g_tile_m[y]; base = g_offp[e];
    }
    int n0 = blockIdx.x * 128;

    const __half* WD = is_shared ? g_sd : g_wd + (size_t)e * HDIM * IDIM;

    int lrow = tid >> 1, kb0 = (tid & 1) * 4;
    uint32_t swo[4];
#pragma unroll
    for (int j = 0; j < 4; j++)
        swo[j] = lrow * 128 + (((kb0 + j) ^ (lrow & 7)) << 4);
    const __half* pA = g_hm + (size_t)(base + m0 + lrow) * IDIM + kb0 * 8;
    const __half* pB = WD + (size_t)(n0 + lrow) * IDIM + kb0 * 8;

    auto issue = [&](int s) {
        int k0 = s * 64;
        uint32_t bb = sb + (s & 1) * DN_STAGE;
#pragma unroll
        for (int j = 0; j < 4; j++) {
            cpasync16(bb + 0 * DN_PART + swo[j], pA + k0 + j * 8);
            cpasync16(bb + 1 * DN_PART + swo[j], pB + k0 + j * 8);
        }
    };

    int warpM = (wid & 1) * 64;
    int warpN = (wid >> 1) * 32;
    int la = lane & 15, kh = lane >> 4, x7 = la & 7;
    uint32_t rowA[4], rowB[2];
#pragma unroll
    for (int mf = 0; mf < 4; mf++) rowA[mf] = (warpM + mf * 16 + la) * 128;
#pragma unroll
    for (int s2 = 0; s2 < 2; s2++) rowB[s2] = (warpN + s2 * 16 + la) * 128;

    float acc[4][4][4];
#pragma unroll
    for (int mf = 0; mf < 4; mf++)
#pragma unroll
        for (int nf = 0; nf < 4; nf++)
#pragma unroll
            for (int q = 0; q < 4; q++) acc[mf][nf][q] = 0.f;

    const int S = IDIM / 64;   // 43
    issue(0); CP_COMMIT();
    for (int s = 0; s < S; s++) {
        if (s < S - 1) { issue(s + 1); CP_COMMIT(); CP_WAIT1(); }
        else CP_WAIT0();
        __syncthreads();
        uint32_t bb = sb + (s & 1) * DN_STAGE;
#pragma unroll
        for (int k16 = 0; k16 < 4; k16++) {
            uint32_t ko = (uint32_t)(((k16 * 2 + kh) ^ x7) << 4);
            uint32_t A[4][4];
#pragma unroll
            for (int mf = 0; mf < 4; mf++)
                ldsm4(A[mf], bb + 0 * DN_PART + rowA[mf] + ko);
            uint32_t B[2][4];
#pragma unroll
            for (int s2 = 0; s2 < 2; s2++)
                ldsm4(B[s2], bb + 1 * DN_PART + rowB[s2] + ko);
#pragma unroll
            for (int mf = 0; mf < 4; mf++)
#pragma unroll
                for (int s2 = 0; s2 < 2; s2++)
#pragma unroll
                    for (int j = 0; j < 2; j++) {
                        int nf = s2 * 2 + j;
                        mma16816(acc[mf][nf], A[mf], B[s2][j], B[s2][2 + j]);
                    }
        }
        __syncthreads();
    }

    int qr = lane >> 2, qc = (lane & 3) * 2;
#pragma unroll
    for (int mf = 0; mf < 4; mf++) {
        int r0 = m0 + warpM + mf * 16 + qr;
        float w0 = is_shared ? 1.f : g_wgt[base + r0];
        float w1 = is_shared ? 1.f : g_wgt[base + r0 + 8];
#pragma unroll
        for (int nf = 0; nf < 4; nf++) {
            int col = n0 + warpN + nf * 8 + qc;
            float* c = acc[mf][nf];
            size_t o0 = (size_t)(base + r0) * HDIM + col;
            size_t o1 = o0 + (size_t)8 * HDIM;
            float2 v0 = make_float2(c[0] * w0, c[1] * w0);
            float2 v1 = make_float2(c[2] * w1, c[3] * w1);
            *(float2*)(g_eo + o0) = v0;
            *(float2*)(g_eo + o1) = v1;
        }
    }
}

// ---------------- combine ----------------
__global__ void combine_kernel(float* __restrict__ out) {
    int idx = blockIdx.x * blockDim.x + threadIdx.x;
    const int HC = HDIM / 4;
    if (idx >= NT * HC) return;
    int t = idx / HC;
    int c = idx - t * HC;
    const float4* eo4 = (const float4*)g_eo;
    int e1 = g_entry_of[2 * t + 0];
    int e2 = g_entry_of[2 * t + 1];
    float4 a = eo4[(size_t)e1 * HC + c];
    float4 b = eo4[(size_t)e2 * HC + c];
    float4 s = eo4[(size_t)(SHB + t) * HC + c];
    float4 r;
    r.x = a.x + b.x + s.x;
    r.y = a.y + b.y + s.y;
    r.z = a.z + b.z + s.z;
    r.w = a.w + b.w + s.w;
    ((float4*)out)[idx] = r;
}

// ---------------- launch ----------------
extern "C" void kernel_launch(void* const* d_in, const int* in_sizes, int n_in,
                              void* d_out, int out_size) {
    const float* x       = (const float*)d_in[0];
    const float* gate_w  = (const float*)d_in[1];
    const float* w_gate  = (const float*)d_in[2];
    const float* w_up    = (const float*)d_in[3];
    const float* w_down  = (const float*)d_in[4];
    const float* ws_gate = (const float*)d_in[5];
    const float* ws_up   = (const float*)d_in[6];
    const float* ws_down = (const float*)d_in[7];
    float* out = (float*)d_out;

    cudaFuncSetAttribute(gateup_mma, cudaFuncAttributeMaxDynamicSharedMemorySize, GU_SMEM);
    cudaFuncSetAttribute(down_mma,   cudaFuncAttributeMaxDynamicSharedMemorySize, DN_SMEM);

    __half *x16, *wg, *wu, *wd, *sg, *su, *sd;
    cudaGetSymbolAddress((void**)&x16, g_x16);
    cudaGetSymbolAddress((void**)&wg, g_wg); cudaGetSymbolAddress((void**)&wu, g_wu);
    cudaGetSymbolAddress((void**)&wd, g_wd);
    cudaGetSymbolAddress((void**)&sg, g_sg); cudaGetSymbolAddress((void**)&su, g_su);
    cudaGetSymbolAddress((void**)&sd, g_sd);

    init_kernel<<<1, 32>>>();
    const int CT = 256;
    int n4;
    n4 = NT * HDIM / 4;
    conv_f16_kernel<<<(n4 + CT - 1) / CT, CT>>>(x, x16, n4);
    n4 = NE * IDIM * HDIM / 4;
    conv_f16_kernel<<<(n4 + CT - 1) / CT, CT>>>(w_gate, wg, n4);
    conv_f16_kernel<<<(n4 + CT - 1) / CT, CT>>>(w_up, wu, n4);
    conv_f16_kernel<<<(n4 + CT - 1) / CT, CT>>>(w_down, wd, n4);
    n4 = IDIM * HDIM / 4;
    conv_f16_kernel<<<(n4 + CT - 1) / CT, CT>>>(ws_gate, sg, n4);
    conv_f16_kernel<<<(n4 + CT - 1) / CT, CT>>>(ws_up, su, n4);
    conv_f16_kernel<<<(n4 + CT - 1) / CT, CT>>>(ws_down, sd, n4);

    gate_kernel<<<NT / 8, 256>>>(x, gate_w);
    scan_kernel<<<1, 32>>>();
    scatter_kernel<<<(NROUTED + 255) / 256, 256>>>();

    gateup_mma<<<dim3((IDIM + 127) / 128, MAXTILES + NT / 128, 1), 256, GU_SMEM>>>();
    down_mma<<<dim3(HDIM / 128, MAXTILES + NT / 128, 1), 256, DN_SMEM>>>();
    combine_kernel<<<(NT * (HDIM / 4) + 255) / 256, 256>>>(out);
}